// round 4
// baseline (speedup 1.0000x reference)
#include <cuda_runtime.h>
#include <math.h>

// Problem constants
#define BATCH 4
#define SEQ 2048
#define NWIRES 8
#define EMBED 512
#define HEADS 8
#define DK 64
#define TOKENS (BATCH * SEQ)          // 8192
#define BH (BATCH * HEADS)            // 32

// scale folded into M: 1/sqrt(64) * log2(e)
#define QSCALE (0.125f * 1.4426950408889634f)

// Scratch (device globals; allocation-free rule)
__device__ float g_proj[TOKENS * 8];     // [t][n], proj = cos(x + theta)
__device__ float g_M[HEADS * 64];        // [h][n][a] = QSCALE * Wq_h^T Wk_h
__device__ float g_u[BH * SEQ * 8];      // [bh][s][a] = proj_s^T M_h
__device__ float g_C[EMBED * 64];        // [f][h*8+a] = (Wc_h @ Wv_h)[f][a]
__device__ float g_A[TOKENS * 64];       // [t][h*8+a] = acc/l

// ---------------------------------------------------------------------------
// P1: proj = cos(x + theta)
// ---------------------------------------------------------------------------
__global__ void __launch_bounds__(256) proj_prep_kernel(
    const float* __restrict__ x, const float* __restrict__ theta)
{
    int i = blockIdx.x * 256 + threadIdx.x;      // 0 .. TOKENS*8-1
    g_proj[i] = cosf(x[i] + theta[i & 7]);
}

// ---------------------------------------------------------------------------
// P2: M_h[n][a] = QSCALE * sum_d Wq[h*64+d][n] * Wk[h*64+d][a]
// 8 blocks (heads) x 64 threads
// ---------------------------------------------------------------------------
__global__ void __launch_bounds__(64) m_prep_kernel(
    const float* __restrict__ Wq, const float* __restrict__ Wk)
{
    int h = blockIdx.x;
    int n = threadIdx.x >> 3, a = threadIdx.x & 7;
    float m = 0.f;
    #pragma unroll 8
    for (int d = 0; d < 64; d++)
        m += Wq[(h * 64 + d) * 8 + n] * Wk[(h * 64 + d) * 8 + a];
    g_M[h * 64 + threadIdx.x] = m * QSCALE;
}

// ---------------------------------------------------------------------------
// P3: u[bh][s][a] = sum_n proj[b][s][n] * M_h[n][a]
// grid (SEQ/256, BH), 256 threads
// ---------------------------------------------------------------------------
__global__ void __launch_bounds__(256) u_prep_kernel()
{
    __shared__ float sM[64];
    int bh = blockIdx.y, b = bh >> 3, h = bh & 7;
    int s = blockIdx.x * 256 + threadIdx.x;
    if (threadIdx.x < 64) sM[threadIdx.x] = g_M[h * 64 + threadIdx.x];
    __syncthreads();

    const float* p = g_proj + ((size_t)b * SEQ + s) * 8;
    float pr[8];
    #pragma unroll
    for (int n = 0; n < 8; n++) pr[n] = p[n];

    float* up = g_u + ((size_t)bh * SEQ + s) * 8;
    #pragma unroll
    for (int a = 0; a < 8; a++) {
        float u = 0.f;
        #pragma unroll
        for (int n = 0; n < 8; n++) u += pr[n] * sM[n * 8 + a];
        up[a] = u;
    }
}

// ---------------------------------------------------------------------------
// P4: C[f][h*8+a] = sum_d Wc[f][h*64+d] * Wv[h*64+d][a]
// grid 512 (f), 64 threads
// ---------------------------------------------------------------------------
__global__ void __launch_bounds__(64) c_prep_kernel(
    const float* __restrict__ Wv, const float* __restrict__ Wc)
{
    int f = blockIdx.x;
    int h = threadIdx.x >> 3, a = threadIdx.x & 7;
    float c = 0.f;
    #pragma unroll 8
    for (int d = 0; d < 64; d++)
        c += Wc[(size_t)f * EMBED + h * 64 + d] * Wv[(h * 64 + d) * 8 + a];
    g_C[f * 64 + threadIdx.x] = c;
}

// ---------------------------------------------------------------------------
// Attention in rank-8 space. One thread = one query row i of one (b,h):
//   s_ij = u_i . proj_j  (8 FFMA);  p = exp2(s);  acc8 += p * proj_j;  l += p
// proj for batch b staged in shared in 2 chunks of 1024 rows (32KB).
// grid (SEQ/128, BH), 128 threads.
// ---------------------------------------------------------------------------
__global__ void __launch_bounds__(128) attn_kernel()
{
    __shared__ float4 sp[2048];   // 1024 rows x 2 float4 = 32KB

    const int tid = threadIdx.x;
    const int bh = blockIdx.y, b = bh >> 3, h = bh & 7;
    const int row = blockIdx.x * 128 + tid;

    const float4* up = (const float4*)(g_u + ((size_t)bh * SEQ + row) * 8);
    const float4 u0 = up[0], u1 = up[1];

    float a0 = 0.f, a1 = 0.f, a2 = 0.f, a3 = 0.f;
    float a4 = 0.f, a5 = 0.f, a6 = 0.f, a7 = 0.f;
    float l = 0.f;

    const float4* pb = (const float4*)(g_proj + (size_t)b * SEQ * 8);

    #pragma unroll 1
    for (int c0 = 0; c0 < 2; c0++) {
        __syncthreads();
        #pragma unroll
        for (int i = 0; i < 16; i++)
            sp[tid + i * 128] = pb[c0 * 2048 + tid + i * 128];
        __syncthreads();

        #pragma unroll 1
        for (int jj = 0; jj < 2048; jj += 8) {
            float4 r00 = sp[jj + 0], r01 = sp[jj + 1];
            float4 r10 = sp[jj + 2], r11 = sp[jj + 3];
            float4 r20 = sp[jj + 4], r21 = sp[jj + 5];
            float4 r30 = sp[jj + 6], r31 = sp[jj + 7];

            float s0 = u0.x*r00.x + u0.y*r00.y + u0.z*r00.z + u0.w*r00.w
                     + u1.x*r01.x + u1.y*r01.y + u1.z*r01.z + u1.w*r01.w;
            float s1 = u0.x*r10.x + u0.y*r10.y + u0.z*r10.z + u0.w*r10.w
                     + u1.x*r11.x + u1.y*r11.y + u1.z*r11.z + u1.w*r11.w;
            float s2 = u0.x*r20.x + u0.y*r20.y + u0.z*r20.z + u0.w*r20.w
                     + u1.x*r21.x + u1.y*r21.y + u1.z*r21.z + u1.w*r21.w;
            float s3 = u0.x*r30.x + u0.y*r30.y + u0.z*r30.z + u0.w*r30.w
                     + u1.x*r31.x + u1.y*r31.y + u1.z*r31.z + u1.w*r31.w;

            float p0 = exp2f(s0), p1 = exp2f(s1);
            float p2 = exp2f(s2), p3 = exp2f(s3);
            l += (p0 + p1) + (p2 + p3);

            a0 += p0*r00.x + p1*r10.x + p2*r20.x + p3*r30.x;
            a1 += p0*r00.y + p1*r10.y + p2*r20.y + p3*r30.y;
            a2 += p0*r00.z + p1*r10.z + p2*r20.z + p3*r30.z;
            a3 += p0*r00.w + p1*r10.w + p2*r20.w + p3*r30.w;
            a4 += p0*r01.x + p1*r11.x + p2*r21.x + p3*r31.x;
            a5 += p0*r01.y + p1*r11.y + p2*r21.y + p3*r31.y;
            a6 += p0*r01.z + p1*r11.z + p2*r21.z + p3*r31.z;
            a7 += p0*r01.w + p1*r11.w + p2*r21.w + p3*r31.w;
        }
    }

    const float inv = 1.0f / l;
    float4* outp = (float4*)(g_A + ((size_t)(b * SEQ + row) * 64 + h * 8));
    outp[0] = make_float4(a0 * inv, a1 * inv, a2 * inv, a3 * inv);
    outp[1] = make_float4(a4 * inv, a5 * inv, a6 * inv, a7 * inv);
}

// ---------------------------------------------------------------------------
// Final: out[t][f] = sum_c A[t][c] * C[f][c].  M=8192, N=512, K=64.
// ---------------------------------------------------------------------------
__global__ void __launch_bounds__(256) out_gemm_kernel(float* __restrict__ out)
{
    __shared__ float As[16][65];   // [k][m]
    __shared__ float Bs[16][65];   // [k][n]

    const int lid = threadIdx.x;
    const int tx = lid & 15, ty = lid >> 4;
    const int m0 = blockIdx.x * 64, n0 = blockIdx.y * 64;

    float acc[4][4];
    #pragma unroll
    for (int i = 0; i < 4; i++)
        #pragma unroll
        for (int j = 0; j < 4; j++) acc[i][j] = 0.f;

    #pragma unroll 1
    for (int k0 = 0; k0 < 64; k0 += 16) {
        #pragma unroll
        for (int i = 0; i < 4; i++) {
            int idx = lid + i * 256;        // 0..1023
            int rr = idx >> 4, kk = idx & 15;
            As[kk][rr] = g_A[(size_t)(m0 + rr) * 64 + k0 + kk];
            Bs[kk][rr] = g_C[(size_t)(n0 + rr) * 64 + k0 + kk];
        }
        __syncthreads();
        #pragma unroll
        for (int kk = 0; kk < 16; kk++) {
            float a[4], bb[4];
            #pragma unroll
            for (int i = 0; i < 4; i++) a[i]  = As[kk][ty * 4 + i];
            #pragma unroll
            for (int j = 0; j < 4; j++) bb[j] = Bs[kk][tx * 4 + j];
            #pragma unroll
            for (int i = 0; i < 4; i++)
                #pragma unroll
                for (int j = 0; j < 4; j++) acc[i][j] += a[i] * bb[j];
        }
        __syncthreads();
    }

    #pragma unroll
    for (int i = 0; i < 4; i++) {
        float* orow = out + (size_t)(m0 + ty * 4 + i) * EMBED + n0 + tx * 4;
        #pragma unroll
        for (int j = 0; j < 4; j++) orow[j] = acc[i][j];
    }
}

// ---------------------------------------------------------------------------
extern "C" void kernel_launch(void* const* d_in, const int* in_sizes, int n_in,
                              void* d_out, int out_size)
{
    (void)in_sizes; (void)n_in; (void)out_size;
    const float* x     = (const float*)d_in[0];
    const float* theta = (const float*)d_in[1];
    const float* Wq    = (const float*)d_in[2];
    const float* Wk    = (const float*)d_in[3];
    const float* Wv    = (const float*)d_in[4];
    const float* Wc    = (const float*)d_in[5];
    float* out = (float*)d_out;

    proj_prep_kernel<<<TOKENS * 8 / 256, 256>>>(x, theta);
    m_prep_kernel<<<HEADS, 64>>>(Wq, Wk);
    c_prep_kernel<<<EMBED, 64>>>(Wv, Wc);

    dim3 ug(SEQ / 256, BH);
    u_prep_kernel<<<ug, 256>>>();

    dim3 ag(SEQ / 128, BH);
    attn_kernel<<<ag, 128>>>();

    dim3 gg(TOKENS / 64, EMBED / 64);
    out_gemm_kernel<<<gg, 256>>>(out);
}

// round 5
// speedup vs baseline: 1.1963x; 1.1963x over previous
#include <cuda_runtime.h>
#include <math.h>

// Problem constants
#define BATCH 4
#define SEQ 2048
#define NWIRES 8
#define EMBED 512
#define HEADS 8
#define DK 64
#define TOKENS (BATCH * SEQ)          // 8192
#define BH (BATCH * HEADS)            // 32

// scale folded into M: 1/sqrt(64) * log2(e)
#define QSCALE (0.125f * 1.4426950408889634f)

typedef unsigned long long u64t;

// ---- packed f32x2 helpers (sm_100+) ----
__device__ __forceinline__ u64t fma2(u64t a, u64t b, u64t c) {
    u64t d; asm("fma.rn.f32x2 %0, %1, %2, %3;" : "=l"(d) : "l"(a), "l"(b), "l"(c)); return d;
}
__device__ __forceinline__ u64t mul2(u64t a, u64t b) {
    u64t d; asm("mul.rn.f32x2 %0, %1, %2;" : "=l"(d) : "l"(a), "l"(b)); return d;
}
__device__ __forceinline__ u64t add2(u64t a, u64t b) {
    u64t d; asm("add.rn.f32x2 %0, %1, %2;" : "=l"(d) : "l"(a), "l"(b)); return d;
}
__device__ __forceinline__ u64t pack2(float lo, float hi) {
    u64t d; asm("mov.b64 %0, {%1, %2};" : "=l"(d) : "f"(lo), "f"(hi)); return d;
}
__device__ __forceinline__ float2 unpack2(u64t v) {
    float lo, hi; asm("mov.b64 {%0, %1}, %2;" : "=f"(lo), "=f"(hi) : "l"(v));
    return make_float2(lo, hi);
}

// Scratch (device globals; allocation-free rule)
__device__ float g_proj[TOKENS * 8];     // [t][n], proj = cos(x + theta)
__device__ float g_M[HEADS * 64];        // [h][n][a] = QSCALE * Wq_h^T Wk_h
__device__ float g_u[BH * SEQ * 8];      // [bh][s][a] = proj_s^T M_h
__device__ float g_C[EMBED * 64];        // [f][h*8+a] = (Wc_h @ Wv_h)[f][a]
// unnormalized partials per j-half
__device__ float g_P0[TOKENS * 64];      // [t][h*8+a]
__device__ float g_P1[TOKENS * 64];
__device__ float g_L0[TOKENS * 8];       // [t][h]
__device__ float g_L1[TOKENS * 8];

// ---------------------------------------------------------------------------
// P1: proj = cos(x + theta)
// ---------------------------------------------------------------------------
__global__ void __launch_bounds__(256) proj_prep_kernel(
    const float* __restrict__ x, const float* __restrict__ theta)
{
    int i = blockIdx.x * 256 + threadIdx.x;      // 0 .. TOKENS*8-1
    g_proj[i] = cosf(x[i] + theta[i & 7]);
}

// ---------------------------------------------------------------------------
// P2: M_h[n][a] = QSCALE * sum_d Wq[h*64+d][n] * Wk[h*64+d][a]
// ---------------------------------------------------------------------------
__global__ void __launch_bounds__(64) m_prep_kernel(
    const float* __restrict__ Wq, const float* __restrict__ Wk)
{
    int h = blockIdx.x;
    int n = threadIdx.x >> 3, a = threadIdx.x & 7;
    float m = 0.f;
    #pragma unroll 8
    for (int d = 0; d < 64; d++)
        m += Wq[(h * 64 + d) * 8 + n] * Wk[(h * 64 + d) * 8 + a];
    g_M[h * 64 + threadIdx.x] = m * QSCALE;
}

// ---------------------------------------------------------------------------
// P3: u[bh][s][a] = sum_n proj[b][s][n] * M_h[n][a]
// ---------------------------------------------------------------------------
__global__ void __launch_bounds__(256) u_prep_kernel()
{
    __shared__ float sM[64];
    int bh = blockIdx.y, b = bh >> 3, h = bh & 7;
    int s = blockIdx.x * 256 + threadIdx.x;
    if (threadIdx.x < 64) sM[threadIdx.x] = g_M[h * 64 + threadIdx.x];
    __syncthreads();

    const float* p = g_proj + ((size_t)b * SEQ + s) * 8;
    float pr[8];
    #pragma unroll
    for (int n = 0; n < 8; n++) pr[n] = p[n];

    float* up = g_u + ((size_t)bh * SEQ + s) * 8;
    #pragma unroll
    for (int a = 0; a < 8; a++) {
        float u = 0.f;
        #pragma unroll
        for (int n = 0; n < 8; n++) u += pr[n] * sM[n * 8 + a];
        up[a] = u;
    }
}

// ---------------------------------------------------------------------------
// P4: C[f][h*8+a] = sum_d Wc[f][h*64+d] * Wv[h*64+d][a]
// ---------------------------------------------------------------------------
__global__ void __launch_bounds__(64) c_prep_kernel(
    const float* __restrict__ Wv, const float* __restrict__ Wc)
{
    int f = blockIdx.x;
    int h = threadIdx.x >> 3, a = threadIdx.x & 7;
    float c = 0.f;
    #pragma unroll 8
    for (int d = 0; d < 64; d++)
        c += Wc[(size_t)f * EMBED + h * 64 + d] * Wv[(h * 64 + d) * 8 + a];
    g_C[f * 64 + threadIdx.x] = c;
}

// ---------------------------------------------------------------------------
// Attention in rank-8 space with packed f32x2 math.
// One thread = one query row i of one (b,h); one block = one j-half (1024 j):
//   s_j = u_i . proj_j;  p = exp2(s);  acc8 += p * proj_j;  l += p
// proj half staged TRANSPOSED in shared as [n][j] so one broadcast LDS.64
// yields (p_j[n], p_{j+1}[n]) and everything runs j-pair-packed via FFMA2.
// Partials (unnormalized) written to g_P{0,1} / g_L{0,1}; no running max
// needed (scores bounded), so halves combine by plain addition later.
// grid (SEQ/128, BH, 2), 128 threads.
// ---------------------------------------------------------------------------
__global__ void __launch_bounds__(128, 5) attn_kernel()
{
    __shared__ __align__(16) float spf[8 * 1024];   // [n][j], 32KB

    const int tid = threadIdx.x;
    const int bh = blockIdx.y, b = bh >> 3, h = bh & 7;
    const int row = blockIdx.x * 128 + tid;
    const int half = blockIdx.z;

    // load u_i and pack to (u,u)
    const float* up = g_u + ((size_t)bh * SEQ + row) * 8;
    u64t u2[8];
    #pragma unroll
    for (int n = 0; n < 8; n++) { float un = up[n]; u2[n] = pack2(un, un); }

    // stage this half's 1024 proj rows, transposed to [n][j]
    const float* pb = g_proj + ((size_t)b * SEQ + half * 1024) * 8;
    #pragma unroll
    for (int i = 0; i < 8; i++) {
        int j = tid + i * 128;
        float4 v0 = ((const float4*)(pb + j * 8))[0];
        float4 v1 = ((const float4*)(pb + j * 8))[1];
        spf[0 * 1024 + j] = v0.x; spf[1 * 1024 + j] = v0.y;
        spf[2 * 1024 + j] = v0.z; spf[3 * 1024 + j] = v0.w;
        spf[4 * 1024 + j] = v1.x; spf[5 * 1024 + j] = v1.y;
        spf[6 * 1024 + j] = v1.z; spf[7 * 1024 + j] = v1.w;
    }
    __syncthreads();

    const u64t* sp2 = (const u64t*)spf;   // [n][512] j-pairs

    u64t accA[8], accB[8];
    #pragma unroll
    for (int n = 0; n < 8; n++) { accA[n] = 0ull; accB[n] = 0ull; }
    u64t l2a = 0ull, l2b = 0ull;

    #pragma unroll 1
    for (int jp = 0; jp < 512; jp += 2) {
        u64t rA[8], rB[8];
        #pragma unroll
        for (int n = 0; n < 8; n++) {
            rA[n] = sp2[n * 512 + jp];
            rB[n] = sp2[n * 512 + jp + 1];
        }
        // scores for j-pair A (2-way split chains)
        u64t sa = fma2(u2[0], rA[0], fma2(u2[2], rA[2], fma2(u2[4], rA[4], mul2(u2[6], rA[6]))));
        u64t sb = fma2(u2[1], rA[1], fma2(u2[3], rA[3], fma2(u2[5], rA[5], mul2(u2[7], rA[7]))));
        float2 sAB = unpack2(add2(sa, sb));
        // scores for j-pair B
        u64t ta = fma2(u2[0], rB[0], fma2(u2[2], rB[2], fma2(u2[4], rB[4], mul2(u2[6], rB[6]))));
        u64t tb = fma2(u2[1], rB[1], fma2(u2[3], rB[3], fma2(u2[5], rB[5], mul2(u2[7], rB[7]))));
        float2 sCD = unpack2(add2(ta, tb));

        float p0 = exp2f(sAB.x), p1 = exp2f(sAB.y);
        float p2 = exp2f(sCD.x), p3 = exp2f(sCD.y);
        u64t pp01 = pack2(p0, p1), pp23 = pack2(p2, p3);
        l2a = add2(l2a, pp01);
        l2b = add2(l2b, pp23);

        #pragma unroll
        for (int n = 0; n < 8; n++) accA[n] = fma2(pp01, rA[n], accA[n]);
        #pragma unroll
        for (int n = 0; n < 8; n++) accB[n] = fma2(pp23, rB[n], accB[n]);
    }

    float2 la = unpack2(l2a), lb = unpack2(l2b);
    float l = (la.x + la.y) + (lb.x + lb.y);

    float acc[8];
    #pragma unroll
    for (int n = 0; n < 8; n++) {
        float2 a = unpack2(accA[n]), bb = unpack2(accB[n]);
        acc[n] = (a.x + a.y) + (bb.x + bb.y);
    }

    const int t = b * SEQ + row;
    float* P = (half ? g_P1 : g_P0) + ((size_t)t * 64 + h * 8);
    ((float4*)P)[0] = make_float4(acc[0], acc[1], acc[2], acc[3]);
    ((float4*)P)[1] = make_float4(acc[4], acc[5], acc[6], acc[7]);
    (half ? g_L1 : g_L0)[t * 8 + h] = l;
}

// ---------------------------------------------------------------------------
// Final: out[t][f] = sum_c A[t][c] * C[f][c], with
//   A[t][h*8+a] = (P0+P1)[t][h*8+a] / (L0+L1)[t][h]   folded into the A-load.
// M=8192, N=512, K=64.
// ---------------------------------------------------------------------------
__global__ void __launch_bounds__(256) out_gemm_kernel(float* __restrict__ out)
{
    __shared__ float As[16][65];    // [k][m]
    __shared__ float Bs[16][65];    // [k][n]
    __shared__ float sinv[64][9];   // [m-local][h] = 1/(L0+L1)

    const int lid = threadIdx.x;
    const int tx = lid & 15, ty = lid >> 4;
    const int m0 = blockIdx.x * 64, n0 = blockIdx.y * 64;

    // stage 1/l for the 64 token rows of this tile
    #pragma unroll
    for (int i = lid; i < 512; i += 256) {
        int rr = i >> 3, hh = i & 7;
        int t = m0 + rr;
        sinv[rr][hh] = 1.0f / (g_L0[t * 8 + hh] + g_L1[t * 8 + hh]);
    }
    __syncthreads();

    float acc[4][4];
    #pragma unroll
    for (int i = 0; i < 4; i++)
        #pragma unroll
        for (int j = 0; j < 4; j++) acc[i][j] = 0.f;

    #pragma unroll 1
    for (int k0 = 0; k0 < 64; k0 += 16) {
        #pragma unroll
        for (int i = 0; i < 4; i++) {
            int idx = lid + i * 256;        // 0..1023
            int rr = idx >> 4, kk = idx & 15;
            size_t ai = (size_t)(m0 + rr) * 64 + k0 + kk;
            As[kk][rr] = (g_P0[ai] + g_P1[ai]) * sinv[rr][(k0 + kk) >> 3];
            Bs[kk][rr] = g_C[(size_t)(n0 + rr) * 64 + k0 + kk];
        }
        __syncthreads();
        #pragma unroll
        for (int kk = 0; kk < 16; kk++) {
            float a[4], bb[4];
            #pragma unroll
            for (int i = 0; i < 4; i++) a[i]  = As[kk][ty * 4 + i];
            #pragma unroll
            for (int j = 0; j < 4; j++) bb[j] = Bs[kk][tx * 4 + j];
            #pragma unroll
            for (int i = 0; i < 4; i++)
                #pragma unroll
                for (int j = 0; j < 4; j++) acc[i][j] += a[i] * bb[j];
        }
        __syncthreads();
    }

    #pragma unroll
    for (int i = 0; i < 4; i++) {
        float* orow = out + (size_t)(m0 + ty * 4 + i) * EMBED + n0 + tx * 4;
        #pragma unroll
        for (int j = 0; j < 4; j++) orow[j] = acc[i][j];
    }
}

// ---------------------------------------------------------------------------
extern "C" void kernel_launch(void* const* d_in, const int* in_sizes, int n_in,
                              void* d_out, int out_size)
{
    (void)in_sizes; (void)n_in; (void)out_size;
    const float* x     = (const float*)d_in[0];
    const float* theta = (const float*)d_in[1];
    const float* Wq    = (const float*)d_in[2];
    const float* Wk    = (const float*)d_in[3];
    const float* Wv    = (const float*)d_in[4];
    const float* Wc    = (const float*)d_in[5];
    float* out = (float*)d_out;

    proj_prep_kernel<<<TOKENS * 8 / 256, 256>>>(x, theta);
    m_prep_kernel<<<HEADS, 64>>>(Wq, Wk);
    c_prep_kernel<<<EMBED, 64>>>(Wv, Wc);

    dim3 ug(SEQ / 256, BH);
    u_prep_kernel<<<ug, 256>>>();

    dim3 ag(SEQ / 128, BH, 2);
    attn_kernel<<<ag, 128>>>();

    dim3 gg(TOKENS / 64, EMBED / 64);
    out_gemm_kernel<<<gg, 256>>>(out);
}